// round 11
// baseline (speedup 1.0000x reference)
#include <cuda_runtime.h>
#include <cuda_fp16.h>
#include <cstdint>

#define NN   100000
#define MPAD 100096            // 782 * 128
#define FEAT 256
#define NT   782
#define SPAD 72
#define EMAX 800000
#define NB   391               // ceil(NN/256)

// block ranges in k_pre
#define PRE_CVTX 25024         // MPAD*64/256
#define PRE_DEGI 3125
#define PRE_W12  512           // 2*256*256/256

// ---------------- device scratch ----------------
__device__ int   g_degi[NN];           // zero-init; k_off restores zeros
__device__ int   g_ctr;
__device__ float g_inv[NN];
__device__ int   g_off[NN];
__device__ int   g_end[NN];
__device__ int   g_cursor[NN];
__device__ int   g_srcl[EMAX];
__device__ __align__(16) __half g_ys[(size_t)MPAD * 256];   // self-transform
__device__ __align__(16) __half g_z [(size_t)MPAD * 256];   // neighbor-transform (L2-resident)
__device__ __align__(16) __half g_h[(size_t)MPAD * FEAT];
__device__ __align__(16) __half g_w[2][512 * 256];
__device__ __align__(16) __half g_w3[128 * 256];

// ---------------- helpers ----------------
__device__ __forceinline__ uint32_t smem_u32(const void* p) {
    uint32_t a;
    asm("{ .reg .u64 t; cvta.to.shared.u64 t, %1; cvt.u32.u64 %0, t; }" : "=r"(a) : "l"(p));
    return a;
}
__device__ __forceinline__ void cpa16(uint32_t dst, const void* src) {
    asm volatile("cp.async.cg.shared.global [%0], [%1], 16;" :: "r"(dst), "l"(src));
}
__device__ __forceinline__ void cvt_w_seg(const float* __restrict__ Ws,
                                          const float* __restrict__ Wn,
                                          int Nw, __half* __restrict__ w, int idx) {
    int n = idx >> 8, k = idx & 255;
    float v = (n < Nw) ? Ws[(size_t)k * Nw + n] : Wn[(size_t)k * Nw + (n - Nw)];
    w[idx] = __float2half_rn(v);
}

// ---------------- fused preprocessing: cvt_x | degi | cvt_w x3 ----------------
__global__ void k_pre(const float* __restrict__ x, const int* __restrict__ dst,
                      const float* __restrict__ Ws1, const float* __restrict__ Wn1,
                      const float* __restrict__ Ws2, const float* __restrict__ Wn2,
                      const float* __restrict__ Ws3, const float* __restrict__ Wn3,
                      int M, int E) {
    int b = blockIdx.x;
    int tid = threadIdx.x;
    if (b == 0 && tid == 0) g_ctr = 0;
    if (b < PRE_CVTX) {
        size_t i4 = (size_t)b * 256 + tid;
        int row = (int)(i4 >> 6);
        float4 v = make_float4(0.f, 0.f, 0.f, 0.f);
        if (row < M) v = reinterpret_cast<const float4*>(x)[i4];
        uint2 o;
        __half2 p0 = __float22half2_rn(make_float2(v.x, v.y));
        __half2 p1 = __float22half2_rn(make_float2(v.z, v.w));
        o.x = *reinterpret_cast<uint32_t*>(&p0);
        o.y = *reinterpret_cast<uint32_t*>(&p1);
        *reinterpret_cast<uint2*>(g_h + i4 * 4) = o;
        return;
    }
    b -= PRE_CVTX;
    if (b < PRE_DEGI) {
        int e = b * 256 + tid;
        if (e < E) atomicAdd(&g_degi[dst[e]], 1);
        return;
    }
    b -= PRE_DEGI;
    if (b < PRE_W12) { cvt_w_seg(Ws1, Wn1, 256, g_w[0], b * 256 + tid); return; }
    b -= PRE_W12;
    if (b < PRE_W12) { cvt_w_seg(Ws2, Wn2, 256, g_w[1], b * 256 + tid); return; }
    b -= PRE_W12;
    cvt_w_seg(Ws3, Wn3, 64, g_w3, b * 256 + tid);
}

// single-pass offsets: block scan + atomic range reservation
__global__ void k_off() {
    __shared__ int s[256];
    __shared__ int base;
    int i = blockIdx.x * 256 + threadIdx.x;
    int deg = (i < NN) ? g_degi[i] : 0;
    s[threadIdx.x] = deg;
    __syncthreads();
    for (int st = 1; st < 256; st <<= 1) {
        int add = (threadIdx.x >= st) ? s[threadIdx.x - st] : 0;
        __syncthreads();
        s[threadIdx.x] += add;
        __syncthreads();
    }
    if (threadIdx.x == 255) base = atomicAdd(&g_ctr, s[255]);
    __syncthreads();
    if (i < NN) {
        int beg = base + s[threadIdx.x] - deg;
        g_off[i] = beg;
        g_end[i] = beg + deg;
        g_cursor[i] = beg;
        g_inv[i] = 1.0f / fmaxf((float)deg, 1.0f);
        g_degi[i] = 0;                    // restore for next replay
    }
}
__global__ void k_fill(const int* __restrict__ src, const int* __restrict__ dst, int E) {
    int e = blockIdx.x * blockDim.x + threadIdx.x;
    if (e < E) {
        int pos = atomicAdd(&g_cursor[dst[e]], 1);
        g_srcl[pos] = src[e];
    }
}

// ---------------- fused gather + combine ----------------
__device__ __forceinline__ void acc8(float* acc, uint4 raw) {
    const __half2* hp = reinterpret_cast<const __half2*>(&raw);
#pragma unroll
    for (int q = 0; q < 4; q++) {
        float2 f = __half22float2(hp[q]);
        acc[q * 2 + 0] += f.x;
        acc[q * 2 + 1] += f.y;
    }
}
// layers 1/2: one warp per node, lane owns 8 cols of 256.
__global__ void k_gather(const float* __restrict__ bias, int M) {
    int wid  = threadIdx.x >> 5;
    int lane = threadIdx.x & 31;
    int node = blockIdx.x * (blockDim.x >> 5) + wid;
    if (node >= M) return;
    int beg = g_off[node], end = g_end[node];
    const __half* z = g_z + lane * 8;
    float acc[8] = {0.f, 0.f, 0.f, 0.f, 0.f, 0.f, 0.f, 0.f};
    int j = beg;
    for (; j + 4 <= end; j += 4) {
        int s0 = g_srcl[j], s1 = g_srcl[j + 1];
        int s2 = g_srcl[j + 2], s3 = g_srcl[j + 3];
        uint4 r0 = *reinterpret_cast<const uint4*>(z + (size_t)s0 * 256);
        uint4 r1 = *reinterpret_cast<const uint4*>(z + (size_t)s1 * 256);
        uint4 r2 = *reinterpret_cast<const uint4*>(z + (size_t)s2 * 256);
        uint4 r3 = *reinterpret_cast<const uint4*>(z + (size_t)s3 * 256);
        acc8(acc, r0); acc8(acc, r1); acc8(acc, r2); acc8(acc, r3);
    }
    for (; j < end; j++) {
        int s0 = g_srcl[j];
        uint4 r0 = *reinterpret_cast<const uint4*>(z + (size_t)s0 * 256);
        acc8(acc, r0);
    }
    float inv = g_inv[node];
    uint4 rs = *reinterpret_cast<const uint4*>(g_ys + (size_t)node * 256 + lane * 8);
    const __half2* sp = reinterpret_cast<const __half2*>(&rs);
    float4 bva = *reinterpret_cast<const float4*>(bias + lane * 8);
    float4 bvb = *reinterpret_cast<const float4*>(bias + lane * 8 + 4);
    float bv[8] = {bva.x, bva.y, bva.z, bva.w, bvb.x, bvb.y, bvb.z, bvb.w};
    float v[8];
#pragma unroll
    for (int q = 0; q < 4; q++) {
        float2 ys = __half22float2(sp[q]);
        v[q * 2 + 0] = fmaxf(ys.x + inv * acc[q * 2 + 0] + bv[q * 2 + 0], 0.f);
        v[q * 2 + 1] = fmaxf(ys.y + inv * acc[q * 2 + 1] + bv[q * 2 + 1], 0.f);
    }
    uint4 o;
    __half2 p0 = __float22half2_rn(make_float2(v[0], v[1]));
    __half2 p1 = __float22half2_rn(make_float2(v[2], v[3]));
    __half2 p2 = __float22half2_rn(make_float2(v[4], v[5]));
    __half2 p3 = __float22half2_rn(make_float2(v[6], v[7]));
    o.x = *reinterpret_cast<uint32_t*>(&p0);
    o.y = *reinterpret_cast<uint32_t*>(&p1);
    o.z = *reinterpret_cast<uint32_t*>(&p2);
    o.w = *reinterpret_cast<uint32_t*>(&p3);
    *reinterpret_cast<uint4*>(g_h + (size_t)node * 256 + lane * 8) = o;
}
// layer 3: 8 lanes per node (4 nodes/warp), lane owns 8 of 64 cols, fp32 out.
__global__ void k_gather3(const float* __restrict__ bias, float* __restrict__ out, int M) {
    int wid  = threadIdx.x >> 5;
    int lane = threadIdx.x & 31;
    int node = (blockIdx.x * (blockDim.x >> 5) + wid) * 4 + (lane >> 3);
    int sub  = lane & 7;
    if (node >= M) return;
    int beg = g_off[node], end = g_end[node];
    const __half* z = g_z + sub * 8;
    float acc[8] = {0.f, 0.f, 0.f, 0.f, 0.f, 0.f, 0.f, 0.f};
    int j = beg;
    for (; j + 4 <= end; j += 4) {
        int s0 = g_srcl[j], s1 = g_srcl[j + 1];
        int s2 = g_srcl[j + 2], s3 = g_srcl[j + 3];
        uint4 r0 = *reinterpret_cast<const uint4*>(z + (size_t)s0 * 64);
        uint4 r1 = *reinterpret_cast<const uint4*>(z + (size_t)s1 * 64);
        uint4 r2 = *reinterpret_cast<const uint4*>(z + (size_t)s2 * 64);
        uint4 r3 = *reinterpret_cast<const uint4*>(z + (size_t)s3 * 64);
        acc8(acc, r0); acc8(acc, r1); acc8(acc, r2); acc8(acc, r3);
    }
    for (; j < end; j++) {
        int s0 = g_srcl[j];
        uint4 r0 = *reinterpret_cast<const uint4*>(z + (size_t)s0 * 64);
        acc8(acc, r0);
    }
    float inv = g_inv[node];
    uint4 rs = *reinterpret_cast<const uint4*>(g_ys + (size_t)node * 64 + sub * 8);
    const __half2* sp = reinterpret_cast<const __half2*>(&rs);
    float4 bva = *reinterpret_cast<const float4*>(bias + sub * 8);
    float4 bvb = *reinterpret_cast<const float4*>(bias + sub * 8 + 4);
    float bv[8] = {bva.x, bva.y, bva.z, bva.w, bvb.x, bvb.y, bvb.z, bvb.w};
    float v[8];
#pragma unroll
    for (int q = 0; q < 4; q++) {
        float2 ys = __half22float2(sp[q]);
        v[q * 2 + 0] = ys.x + inv * acc[q * 2 + 0] + bv[q * 2 + 0];
        v[q * 2 + 1] = ys.y + inv * acc[q * 2 + 1] + bv[q * 2 + 1];
    }
    float* op = out + (size_t)node * 64 + sub * 8;
    *reinterpret_cast<float4*>(op)     = make_float4(v[0], v[1], v[2], v[3]);
    *reinterpret_cast<float4*>(op + 4) = make_float4(v[4], v[5], v[6], v[7]);
}

// ---------------- fp16 HMMA GEMM: 256 threads, 8 warps (2m x 4n), warp tile 64x32 ----------------
// CTA tile 128 x 128, BK=64, 3-stage cp.async, 2 CTAs/SM, single sync per chunk.
// Epilogue splits output columns: col < NOUT/2 -> Yys, else -> Yz (both row stride NOUT/2).
__global__ __launch_bounds__(256, 2) void k_mma(
    const __half* __restrict__ A, const __half* __restrict__ B,
    __half* __restrict__ Yys, __half* __restrict__ Yz, int NOUT)
{
    extern __shared__ __half dyn[];
    constexpr int AS  = 128 * SPAD;
    constexpr int STG = 2 * AS;

    const int t    = threadIdx.x;
    const int wid  = t >> 5;
    const int lane = t & 31;
    const int wm0  = (wid >> 2) << 6;
    const int wn0  = (wid & 3) << 5;
    const int row0 = blockIdx.y * 128;
    const int col0 = blockIdx.x * 128;

    const int lr = t >> 3;
    const int lc = (t & 7) << 3;

    float acc[4][4][4];
#pragma unroll
    for (int mi = 0; mi < 4; mi++)
#pragma unroll
        for (int ni = 0; ni < 4; ni++)
#pragma unroll
            for (int r = 0; r < 4; r++) acc[mi][ni][r] = 0.0f;

    auto load_chunk = [&](int kc, int s) {
        __half* dA = dyn + s * STG;
        __half* dB = dA + AS;
        const __half* ap = A + (size_t)row0 * FEAT + kc * 64;
        const __half* bp = B + (size_t)col0 * FEAT + kc * 64;
#pragma unroll
        for (int j = 0; j < 4; j++) {
            int row = lr + j * 32;
            cpa16(smem_u32(dA + row * SPAD + lc), ap + (size_t)row * FEAT + lc);
            cpa16(smem_u32(dB + row * SPAD + lc), bp + (size_t)row * FEAT + lc);
        }
        asm volatile("cp.async.commit_group;" ::: "memory");
    };

    load_chunk(0, 0);
    load_chunk(1, 1);

#pragma unroll
    for (int kc = 0; kc < 4; kc++) {
        const int s = kc % 3;
        if (kc < 3) asm volatile("cp.async.wait_group 1;" ::: "memory");
        else        asm volatile("cp.async.wait_group 0;" ::: "memory");
        __syncthreads();
        // buffer (kc+2)%3 was consumed in iteration kc-1; the sync above proves
        // all warps are past it -> safe to refill now, overlapping compute(kc).
        if (kc + 2 < 4) load_chunk(kc + 2, (kc + 2) % 3);

        __half* dA = dyn + s * STG;
        __half* dB = dA + AS;

#pragma unroll
        for (int ks = 0; ks < 4; ks++) {
            const int k0 = ks << 4;
            const int arow = wm0 + (lane & 15);
            const int acol = k0 + ((lane >> 4) << 3);
            const int brow = wn0 + (lane & 7) + ((lane >> 4) << 3);
            const int bcol = k0 + (((lane >> 3) & 1) << 3);

            uint32_t a[4][4], b[8];
#pragma unroll
            for (int mi = 0; mi < 4; mi++) {
                uint32_t ad = smem_u32(dA + (arow + mi * 16) * SPAD + acol);
                asm volatile("ldmatrix.sync.aligned.m8n8.x4.shared.b16 {%0,%1,%2,%3}, [%4];"
                             : "=r"(a[mi][0]), "=r"(a[mi][1]), "=r"(a[mi][2]), "=r"(a[mi][3])
                             : "r"(ad));
            }
#pragma unroll
            for (int nb = 0; nb < 2; nb++) {
                uint32_t ad = smem_u32(dB + (brow + nb * 16) * SPAD + bcol);
                asm volatile("ldmatrix.sync.aligned.m8n8.x4.shared.b16 {%0,%1,%2,%3}, [%4];"
                             : "=r"(b[nb * 4 + 0]), "=r"(b[nb * 4 + 1]),
                               "=r"(b[nb * 4 + 2]), "=r"(b[nb * 4 + 3])
                             : "r"(ad));
            }
#pragma unroll
            for (int mi = 0; mi < 4; mi++)
#pragma unroll
                for (int ni = 0; ni < 4; ni++)
                    asm volatile(
                        "mma.sync.aligned.m16n8k16.row.col.f32.f16.f16.f32 "
                        "{%0,%1,%2,%3}, {%4,%5,%6,%7}, {%8,%9}, {%0,%1,%2,%3};"
                        : "+f"(acc[mi][ni][0]), "+f"(acc[mi][ni][1]),
                          "+f"(acc[mi][ni][2]), "+f"(acc[mi][ni][3])
                        : "r"(a[mi][0]), "r"(a[mi][1]), "r"(a[mi][2]), "r"(a[mi][3]),
                          "r"(b[ni * 2]), "r"(b[ni * 2 + 1]));
        }
        if (kc < 3) __syncthreads();
    }

    const int half = NOUT >> 1;
    const int crow = lane >> 2;
    const int ccol = (lane & 3) << 1;
#pragma unroll
    for (int mi = 0; mi < 4; mi++)
#pragma unroll
        for (int ni = 0; ni < 4; ni++) {
            int col = col0 + wn0 + ni * 8 + ccol;
            __half* dst = (col < half) ? Yys : Yz;
            int c2 = (col < half) ? col : col - half;
#pragma unroll
            for (int h = 0; h < 2; h++) {
                int row = row0 + wm0 + mi * 16 + crow + h * 8;
                __half2 p = __float22half2_rn(
                    make_float2(acc[mi][ni][h * 2 + 0], acc[mi][ni][h * 2 + 1]));
                *reinterpret_cast<uint32_t*>(dst + (size_t)row * half + c2) =
                    *reinterpret_cast<uint32_t*>(&p);
            }
        }
}

// ---------------- launch ----------------
extern "C" void kernel_launch(void* const* d_in, const int* in_sizes, int n_in,
                              void* d_out, int out_size) {
    const float* x   = (const float*)d_in[0];
    const int*   src = (const int*)d_in[1];
    const int*   dst = (const int*)d_in[2];
    const float* Ws1 = (const float*)d_in[3];
    const float* Wn1 = (const float*)d_in[4];
    const float* b1  = (const float*)d_in[5];
    const float* Ws2 = (const float*)d_in[6];
    const float* Wn2 = (const float*)d_in[7];
    const float* b2  = (const float*)d_in[8];
    const float* Ws3 = (const float*)d_in[9];
    const float* Wn3 = (const float*)d_in[10];
    const float* b3  = (const float*)d_in[11];
    float* out = (float*)d_out;

    const int N = in_sizes[0] / FEAT;   // 100000
    const int E = in_sizes[1];          // 800000

    __half *ys, *z, *h, *w0, *w1, *w3;
    cudaGetSymbolAddress((void**)&ys, g_ys);
    cudaGetSymbolAddress((void**)&z,  g_z);
    cudaGetSymbolAddress((void**)&h,  g_h);
    cudaGetSymbolAddress((void**)&w0, g_w);
    cudaGetSymbolAddress((void**)&w3, g_w3);
    w1 = w0 + (size_t)512 * 256;

    constexpr int SM = 128 * SPAD * 2 * 3 * 2;   // 110592 B
    cudaFuncSetAttribute(k_mma, cudaFuncAttributeMaxDynamicSharedMemorySize, SM);

    const int ZT = 256;
    const int preBlocks = PRE_CVTX + PRE_DEGI + PRE_W12 + PRE_W12 + 128;

    // fused preprocessing: cvt_x | degi | cvt_w x3
    k_pre<<<preBlocks, ZT>>>(x, dst, Ws1, Wn1, Ws2, Wn2, Ws3, Wn3, N, E);
    k_off<<<NB, 256>>>();
    k_fill<<<(E + ZT - 1) / ZT, ZT>>>(src, dst, E);

    dim3 g12(4, NT);
    dim3 g3(1, NT);
    const int gatherB = (N + 7) / 8;
    const int gather3B = (N + 31) / 32;

    // layer 1
    k_mma<<<g12, 256, SM>>>(h, w0, ys, z, 512);
    k_gather<<<gatherB, 256>>>(b1, N);

    // layer 2
    k_mma<<<g12, 256, SM>>>(h, w1, ys, z, 512);
    k_gather<<<gatherB, 256>>>(b2, N);

    // layer 3
    k_mma<<<g3, 256, SM>>>(h, w3, ys, z, 128);
    k_gather3<<<gather3B, 256>>>(b3, out, N);
}

// round 12
// speedup vs baseline: 1.0272x; 1.0272x over previous
#include <cuda_runtime.h>
#include <cuda_fp16.h>
#include <cstdint>

#define NN   100000
#define MPAD 100096            // 782 * 128
#define FEAT 256
#define NT   782
#define SPAD 72
#define EMAX 800000
#define NB   391               // ceil(NN/256)

// k_pre block ranges: degi | cvt_w x3
#define PRE_DEGI 3125
#define PRE_W12  512           // 2*256*256/256
// k_fill block ranges: fill | cvt_x (16B granularity)
#define FIL_E    3125
#define FIL_CVTX 12512         // MPAD*256/8/256

// ---------------- device scratch ----------------
__device__ int   g_degi[NN];           // zero-init; k_off restores zeros
__device__ int   g_ctr;
__device__ float g_inv[NN];
__device__ int   g_off[NN];
__device__ int   g_end[NN];
__device__ int   g_cursor[NN];
__device__ int   g_srcl[EMAX];
__device__ __align__(16) __half g_yz[(size_t)MPAD * 512];
__device__ __align__(16) __half g_h[(size_t)MPAD * FEAT];
__device__ __align__(16) __half g_w[2][512 * 256];
__device__ __align__(16) __half g_w3[128 * 256];

// ---------------- helpers ----------------
__device__ __forceinline__ uint32_t smem_u32(const void* p) {
    uint32_t a;
    asm("{ .reg .u64 t; cvta.to.shared.u64 t, %1; cvt.u32.u64 %0, t; }" : "=r"(a) : "l"(p));
    return a;
}
__device__ __forceinline__ void cpa16(uint32_t dst, const void* src) {
    asm volatile("cp.async.cg.shared.global [%0], [%1], 16;" :: "r"(dst), "l"(src));
}
__device__ __forceinline__ void cvt_w_seg(const float* __restrict__ Ws,
                                          const float* __restrict__ Wn,
                                          int Nw, __half* __restrict__ w, int idx) {
    int n = idx >> 8, k = idx & 255;
    float v = (n < Nw) ? __ldg(&Ws[(size_t)k * Nw + n]) : __ldg(&Wn[(size_t)k * Nw + (n - Nw)]);
    w[idx] = __float2half_rn(v);
}

// ---------------- k_pre: degi | cvt_w x3 (small; unblocks CSR chain fast) ----------------
__global__ void k_pre(const int* __restrict__ dst,
                      const float* __restrict__ Ws1, const float* __restrict__ Wn1,
                      const float* __restrict__ Ws2, const float* __restrict__ Wn2,
                      const float* __restrict__ Ws3, const float* __restrict__ Wn3,
                      int E) {
    int b = blockIdx.x;
    int tid = threadIdx.x;
    if (b == 0 && tid == 0) g_ctr = 0;
    if (b < PRE_DEGI) {
        int e = b * 256 + tid;
        if (e < E) atomicAdd(&g_degi[__ldg(&dst[e])], 1);
        return;
    }
    b -= PRE_DEGI;
    if (b < PRE_W12) { cvt_w_seg(Ws1, Wn1, 256, g_w[0], b * 256 + tid); return; }
    b -= PRE_W12;
    if (b < PRE_W12) { cvt_w_seg(Ws2, Wn2, 256, g_w[1], b * 256 + tid); return; }
    b -= PRE_W12;
    cvt_w_seg(Ws3, Wn3, 64, g_w3, b * 256 + tid);
}

// single-pass offsets: block scan + atomic range reservation
__global__ void k_off() {
    __shared__ int s[256];
    __shared__ int base;
    int i = blockIdx.x * 256 + threadIdx.x;
    int deg = (i < NN) ? g_degi[i] : 0;
    s[threadIdx.x] = deg;
    __syncthreads();
    for (int st = 1; st < 256; st <<= 1) {
        int add = (threadIdx.x >= st) ? s[threadIdx.x - st] : 0;
        __syncthreads();
        s[threadIdx.x] += add;
        __syncthreads();
    }
    if (threadIdx.x == 255) base = atomicAdd(&g_ctr, s[255]);
    __syncthreads();
    if (i < NN) {
        int beg = base + s[threadIdx.x] - deg;
        g_off[i] = beg;
        g_end[i] = beg + deg;
        g_cursor[i] = beg;
        g_inv[i] = 1.0f / fmaxf((float)deg, 1.0f);
        g_degi[i] = 0;                    // restore for next replay
    }
}
// k_fill: CSR bucket fill | cvt_x backfill (independent work to cover atomic latency)
__global__ void k_fill(const int* __restrict__ src, const int* __restrict__ dst,
                       const float* __restrict__ x, int M, int E) {
    int b = blockIdx.x;
    int tid = threadIdx.x;
    if (b < FIL_E) {
        int e = b * 256 + tid;
        if (e < E) {
            int pos = atomicAdd(&g_cursor[__ldg(&dst[e])], 1);
            g_srcl[pos] = __ldg(&src[e]);
        }
        return;
    }
    b -= FIL_E;
    // cvt_x: 8 floats -> 8 halves per thread (16B store)
    size_t i8 = (size_t)b * 256 + tid;
    int row = (int)(i8 >> 5);
    float4 v0 = make_float4(0.f, 0.f, 0.f, 0.f);
    float4 v1 = v0;
    if (row < M) {
        const float4* xp = reinterpret_cast<const float4*>(x) + i8 * 2;
        v0 = __ldg(xp);
        v1 = __ldg(xp + 1);
    }
    uint4 o;
    __half2 p0 = __float22half2_rn(make_float2(v0.x, v0.y));
    __half2 p1 = __float22half2_rn(make_float2(v0.z, v0.w));
    __half2 p2 = __float22half2_rn(make_float2(v1.x, v1.y));
    __half2 p3 = __float22half2_rn(make_float2(v1.z, v1.w));
    o.x = *reinterpret_cast<uint32_t*>(&p0);
    o.y = *reinterpret_cast<uint32_t*>(&p1);
    o.z = *reinterpret_cast<uint32_t*>(&p2);
    o.w = *reinterpret_cast<uint32_t*>(&p3);
    *reinterpret_cast<uint4*>(g_h + i8 * 8) = o;
}

// ---------------- fused gather + combine ----------------
__device__ __forceinline__ void acc8(float* acc, uint4 raw) {
    const __half2* hp = reinterpret_cast<const __half2*>(&raw);
#pragma unroll
    for (int q = 0; q < 4; q++) {
        float2 f = __half22float2(hp[q]);
        acc[q * 2 + 0] += f.x;
        acc[q * 2 + 1] += f.y;
    }
}
// layers 1/2: one warp per node, lane owns 8 cols of 256.
__global__ void k_gather(const float* __restrict__ bias, int M) {
    int wid  = threadIdx.x >> 5;
    int lane = threadIdx.x & 31;
    int node = blockIdx.x * (blockDim.x >> 5) + wid;
    if (node >= M) return;
    int beg = g_off[node], end = g_end[node];
    const __half* z = g_yz + 256 + lane * 8;   // z-half of yz rows
    float acc[8] = {0.f, 0.f, 0.f, 0.f, 0.f, 0.f, 0.f, 0.f};
    int j = beg;
    for (; j + 4 <= end; j += 4) {
        int s0 = __ldg(&g_srcl[j]),     s1 = __ldg(&g_srcl[j + 1]);
        int s2 = __ldg(&g_srcl[j + 2]), s3 = __ldg(&g_srcl[j + 3]);
        uint4 r0 = __ldg(reinterpret_cast<const uint4*>(z + (size_t)s0 * 512));
        uint4 r1 = __ldg(reinterpret_cast<const uint4*>(z + (size_t)s1 * 512));
        uint4 r2 = __ldg(reinterpret_cast<const uint4*>(z + (size_t)s2 * 512));
        uint4 r3 = __ldg(reinterpret_cast<const uint4*>(z + (size_t)s3 * 512));
        acc8(acc, r0); acc8(acc, r1); acc8(acc, r2); acc8(acc, r3);
    }
    for (; j < end; j++) {
        int s0 = __ldg(&g_srcl[j]);
        uint4 r0 = __ldg(reinterpret_cast<const uint4*>(z + (size_t)s0 * 512));
        acc8(acc, r0);
    }
    float inv = g_inv[node];
    uint4 rs = __ldg(reinterpret_cast<const uint4*>(g_yz + (size_t)node * 512 + lane * 8));
    const __half2* sp = reinterpret_cast<const __half2*>(&rs);
    float4 bva = __ldg(reinterpret_cast<const float4*>(bias + lane * 8));
    float4 bvb = __ldg(reinterpret_cast<const float4*>(bias + lane * 8 + 4));
    float bv[8] = {bva.x, bva.y, bva.z, bva.w, bvb.x, bvb.y, bvb.z, bvb.w};
    float v[8];
#pragma unroll
    for (int q = 0; q < 4; q++) {
        float2 ys = __half22float2(sp[q]);
        v[q * 2 + 0] = fmaxf(ys.x + inv * acc[q * 2 + 0] + bv[q * 2 + 0], 0.f);
        v[q * 2 + 1] = fmaxf(ys.y + inv * acc[q * 2 + 1] + bv[q * 2 + 1], 0.f);
    }
    uint4 o;
    __half2 p0 = __float22half2_rn(make_float2(v[0], v[1]));
    __half2 p1 = __float22half2_rn(make_float2(v[2], v[3]));
    __half2 p2 = __float22half2_rn(make_float2(v[4], v[5]));
    __half2 p3 = __float22half2_rn(make_float2(v[6], v[7]));
    o.x = *reinterpret_cast<uint32_t*>(&p0);
    o.y = *reinterpret_cast<uint32_t*>(&p1);
    o.z = *reinterpret_cast<uint32_t*>(&p2);
    o.w = *reinterpret_cast<uint32_t*>(&p3);
    *reinterpret_cast<uint4*>(g_h + (size_t)node * 256 + lane * 8) = o;
}
// layer 3: 8 lanes per node (4 nodes/warp), lane owns 8 of 64 cols, fp32 out.
__global__ void k_gather3(const float* __restrict__ bias, float* __restrict__ out, int M) {
    int wid  = threadIdx.x >> 5;
    int lane = threadIdx.x & 31;
    int node = (blockIdx.x * (blockDim.x >> 5) + wid) * 4 + (lane >> 3);
    int sub  = lane & 7;
    if (node >= M) return;
    int beg = g_off[node], end = g_end[node];
    const __half* z = g_yz + 64 + sub * 8;
    float acc[8] = {0.f, 0.f, 0.f, 0.f, 0.f, 0.f, 0.f, 0.f};
    int j = beg;
    for (; j + 4 <= end; j += 4) {
        int s0 = __ldg(&g_srcl[j]),     s1 = __ldg(&g_srcl[j + 1]);
        int s2 = __ldg(&g_srcl[j + 2]), s3 = __ldg(&g_srcl[j + 3]);
        uint4 r0 = __ldg(reinterpret_cast<const uint4*>(z + (size_t)s0 * 128));
        uint4 r1 = __ldg(reinterpret_cast<const uint4*>(z + (size_t)s1 * 128));
        uint4 r2 = __ldg(reinterpret_cast<const uint4*>(z + (size_t)s2 * 128));
        uint4 r3 = __ldg(reinterpret_cast<const uint4*>(z + (size_t)s3 * 128));
        acc8(acc, r0); acc8(acc, r1); acc8(acc, r2); acc8(acc, r3);
    }
    for (; j < end; j++) {
        int s0 = __ldg(&g_srcl[j]);
        uint4 r0 = __ldg(reinterpret_cast<const uint4*>(z + (size_t)s0 * 128));
        acc8(acc, r0);
    }
    float inv = g_inv[node];
    uint4 rs = __ldg(reinterpret_cast<const uint4*>(g_yz + (size_t)node * 128 + sub * 8));
    const __half2* sp = reinterpret_cast<const __half2*>(&rs);
    float4 bva = __ldg(reinterpret_cast<const float4*>(bias + sub * 8));
    float4 bvb = __ldg(reinterpret_cast<const float4*>(bias + sub * 8 + 4));
    float bv[8] = {bva.x, bva.y, bva.z, bva.w, bvb.x, bvb.y, bvb.z, bvb.w};
    float v[8];
#pragma unroll
    for (int q = 0; q < 4; q++) {
        float2 ys = __half22float2(sp[q]);
        v[q * 2 + 0] = ys.x + inv * acc[q * 2 + 0] + bv[q * 2 + 0];
        v[q * 2 + 1] = ys.y + inv * acc[q * 2 + 1] + bv[q * 2 + 1];
    }
    float* op = out + (size_t)node * 64 + sub * 8;
    *reinterpret_cast<float4*>(op)     = make_float4(v[0], v[1], v[2], v[3]);
    *reinterpret_cast<float4*>(op + 4) = make_float4(v[4], v[5], v[6], v[7]);
}

// ---------------- fp16 HMMA GEMM (R10 config): 256 thr, 8 warps (2m x 4n), 64x32 warp tile ----------------
// CTA tile 128x128, BK=64, 3-stage cp.async, 2 CTAs/SM.
__global__ __launch_bounds__(256, 2) void k_mma(
    const __half* __restrict__ A, const __half* __restrict__ B,
    __half* __restrict__ Y, int NOUT)
{
    extern __shared__ __half dyn[];
    constexpr int AS  = 128 * SPAD;
    constexpr int STG = 2 * AS;

    const int t    = threadIdx.x;
    const int wid  = t >> 5;
    const int lane = t & 31;
    const int wm0  = (wid >> 2) << 6;
    const int wn0  = (wid & 3) << 5;
    const int row0 = blockIdx.y * 128;
    const int col0 = blockIdx.x * 128;

    const int lr = t >> 3;
    const int lc = (t & 7) << 3;

    float acc[4][4][4];
#pragma unroll
    for (int mi = 0; mi < 4; mi++)
#pragma unroll
        for (int ni = 0; ni < 4; ni++)
#pragma unroll
            for (int r = 0; r < 4; r++) acc[mi][ni][r] = 0.0f;

    auto load_chunk = [&](int kc, int s) {
        __half* dA = dyn + s * STG;
        __half* dB = dA + AS;
        const __half* ap = A + (size_t)row0 * FEAT + kc * 64;
        const __half* bp = B + (size_t)col0 * FEAT + kc * 64;
#pragma unroll
        for (int j = 0; j < 4; j++) {
            int row = lr + j * 32;
            cpa16(smem_u32(dA + row * SPAD + lc), ap + (size_t)row * FEAT + lc);
            cpa16(smem_u32(dB + row * SPAD + lc), bp + (size_t)row * FEAT + lc);
        }
        asm volatile("cp.async.commit_group;" ::: "memory");
    };

    load_chunk(0, 0);
    load_chunk(1, 1);

#pragma unroll
    for (int kc = 0; kc < 4; kc++) {
        const int s = kc % 3;
        if (kc + 2 < 4) {
            load_chunk(kc + 2, (kc + 2) % 3);
            asm volatile("cp.async.wait_group 2;" ::: "memory");
        } else if (kc + 1 < 4) {
            asm volatile("cp.async.wait_group 1;" ::: "memory");
        } else {
            asm volatile("cp.async.wait_group 0;" ::: "memory");
        }
        __syncthreads();

        __half* dA = dyn + s * STG;
        __half* dB = dA + AS;

#pragma unroll
        for (int ks = 0; ks < 4; ks++) {
            const int k0 = ks << 4;
            const int arow = wm0 + (lane & 15);
            const int acol = k0 + ((lane >> 4) << 3);
            const int brow = wn0 + (lane & 7) + ((lane >> 4) << 3);
            const int bcol = k0 + (((lane >> 3) & 1) << 3);

            uint32_t a[4][4], b[8];
#pragma unroll
            for (int mi = 0; mi < 4; mi++) {
                uint32_t ad = smem_u32(dA + (arow + mi * 16) * SPAD + acol);
                asm volatile("ldmatrix.sync.aligned.m8n8.x4.shared.b16 {%0,%1,%2,%3}, [%4];"
                             : "=r"(a[mi][0]), "=r"(a[mi][1]), "=r"(a[mi][2]), "=r"(a[mi][3])
                             : "r"(ad));
            }
#pragma unroll
            for (int nb = 0; nb < 2; nb++) {
                uint32_t ad = smem_u32(dB + (brow + nb * 16) * SPAD + bcol);
                asm volatile("ldmatrix.sync.aligned.m8n8.x4.shared.b16 {%0,%1,%2,%3}, [%4];"
                             : "=r"(b[nb * 4 + 0]), "=r"(b[nb * 4 + 1]),
                               "=r"(b[nb * 4 + 2]), "=r"(b[nb * 4 + 3])
                             : "r"(ad));
            }
#pragma unroll
            for (int mi = 0; mi < 4; mi++)
#pragma unroll
                for (int ni = 0; ni < 4; ni++)
                    asm volatile(
                        "mma.sync.aligned.m16n8k16.row.col.f32.f16.f16.f32 "
                        "{%0,%1,%2,%3}, {%4,%5,%6,%7}, {%8,%9}, {%0,%1,%2,%3};"
                        : "+f"(acc[mi][ni][0]), "+f"(acc[mi][ni][1]),
                          "+f"(acc[mi][ni][2]), "+f"(acc[mi][ni][3])
                        : "r"(a[mi][0]), "r"(a[mi][1]), "r"(a[mi][2]), "r"(a[mi][3]),
                          "r"(b[ni * 2]), "r"(b[ni * 2 + 1]));
        }
        __syncthreads();
    }

    const int crow = lane >> 2;
    const int ccol = (lane & 3) << 1;
#pragma unroll
    for (int mi = 0; mi < 4; mi++)
#pragma unroll
        for (int ni = 0; ni < 4; ni++) {
            int col = col0 + wn0 + ni * 8 + ccol;
#pragma unroll
            for (int h = 0; h < 2; h++) {
                int row = row0 + wm0 + mi * 16 + crow + h * 8;
                __half2 p = __float22half2_rn(
                    make_float2(acc[mi][ni][h * 2 + 0], acc[mi][ni][h * 2 + 1]));
                *reinterpret_cast<uint32_t*>(Y + (size_t)row * NOUT + col) =
                    *reinterpret_cast<uint32_t*>(&p);
            }
        }
}

// ---------------- launch ----------------
extern "C" void kernel_launch(void* const* d_in, const int* in_sizes, int n_in,
                              void* d_out, int out_size) {
    const float* x   = (const float*)d_in[0];
    const int*   src = (const int*)d_in[1];
    const int*   dst = (const int*)d_in[2];
    const float* Ws1 = (const float*)d_in[3];
    const float* Wn1 = (const float*)d_in[4];
    const float* b1  = (const float*)d_in[5];
    const float* Ws2 = (const float*)d_in[6];
    const float* Wn2 = (const float*)d_in[7];
    const float* b2  = (const float*)d_in[8];
    const float* Ws3 = (const float*)d_in[9];
    const float* Wn3 = (const float*)d_in[10];
    const float* b3  = (const float*)d_in[11];
    float* out = (float*)d_out;

    const int N = in_sizes[0] / FEAT;   // 100000
    const int E = in_sizes[1];          // 800000

    __half *yz, *h, *w0, *w1, *w3;
    cudaGetSymbolAddress((void**)&yz, g_yz);
    cudaGetSymbolAddress((void**)&h,  g_h);
    cudaGetSymbolAddress((void**)&w0, g_w);
    cudaGetSymbolAddress((void**)&w3, g_w3);
    w1 = w0 + (size_t)512 * 256;

    constexpr int SM = 128 * SPAD * 2 * 3 * 2;   // 110592 B
    cudaFuncSetAttribute(k_mma, cudaFuncAttributeMaxDynamicSharedMemorySize, SM);

    const int ZT = 256;

    // CSR chain with cvt_x backfilled into k_fill
    k_pre<<<PRE_DEGI + 2 * PRE_W12 + 128, ZT>>>(dst, Ws1, Wn1, Ws2, Wn2, Ws3, Wn3, E);
    k_off<<<NB, 256>>>();
    k_fill<<<FIL_E + FIL_CVTX, ZT>>>(src, dst, x, N, E);

    dim3 g12(4, NT);
    dim3 g3(1, NT);
    const int gatherB = (N + 7) / 8;
    const int gather3B = (N + 31) / 32;

    // layer 1
    k_mma<<<g12, 256, SM>>>(h, w0, yz, 512);
    k_gather<<<gatherB, 256>>>(b1, N);

    // layer 2
    k_mma<<<g12, 256, SM>>>(h, w1, yz, 512);
    k_gather<<<gatherB, 256>>>(b2, N);

    // layer 3
    k_mma<<<g3, 256, SM>>>(h, w3, yz, 128);
    k_gather3<<<gather3B, 256>>>(b3, out, N);
}

// round 13
// speedup vs baseline: 1.2246x; 1.1922x over previous
#include <cuda.h>
#include <cuda_runtime.h>
#include <cuda_fp16.h>
#include <cstdint>

#define NN   100000
#define MPAD 100096            // 782 * 128
#define FEAT 256
#define NT   782
#define EMAX 800000
#define NB   391               // ceil(NN/256)

// k_pre block ranges: degi | cvt_w x3
#define PRE_DEGI 3125
#define PRE_W12  512
// k_fill block ranges: fill | cvt_x
#define FIL_E    3125
#define FIL_CVTX 12512         // MPAD*256/8/256

// ---------------- device scratch ----------------
__device__ int   g_degi[NN];
__device__ int   g_ctr;
__device__ float g_inv[NN];
__device__ int   g_off[NN];
__device__ int   g_end[NN];
__device__ int   g_cursor[NN];
__device__ int   g_srcl[EMAX];
__device__ __align__(16) __half g_yz[(size_t)MPAD * 512];
__device__ __align__(16) __half g_h[(size_t)MPAD * FEAT];
__device__ __align__(16) __half g_w[2][512 * 256];
__device__ __align__(16) __half g_w3[128 * 256];

// ---------------- helpers ----------------
__device__ __forceinline__ uint32_t smem_u32(const void* p) {
    uint32_t a;
    asm("{ .reg .u64 t; cvta.to.shared.u64 t, %1; cvt.u32.u64 %0, t; }" : "=r"(a) : "l"(p));
    return a;
}
#define SWZ(off) ((off) ^ (((off) >> 3) & 0x70))

__device__ __forceinline__ void cvt_w_seg(const float* __restrict__ Ws,
                                          const float* __restrict__ Wn,
                                          int Nw, __half* __restrict__ w, int idx) {
    int n = idx >> 8, k = idx & 255;
    float v = (n < Nw) ? __ldg(&Ws[(size_t)k * Nw + n]) : __ldg(&Wn[(size_t)k * Nw + (n - Nw)]);
    w[idx] = __float2half_rn(v);
}

// ---------------- k_pre: degi | cvt_w x3 ----------------
__global__ void k_pre(const int* __restrict__ dst,
                      const float* __restrict__ Ws1, const float* __restrict__ Wn1,
                      const float* __restrict__ Ws2, const float* __restrict__ Wn2,
                      const float* __restrict__ Ws3, const float* __restrict__ Wn3,
                      int E) {
    int b = blockIdx.x;
    int tid = threadIdx.x;
    if (b == 0 && tid == 0) g_ctr = 0;
    if (b < PRE_DEGI) {
        int e = b * 256 + tid;
        if (e < E) atomicAdd(&g_degi[__ldg(&dst[e])], 1);
        return;
    }
    b -= PRE_DEGI;
    if (b < PRE_W12) { cvt_w_seg(Ws1, Wn1, 256, g_w[0], b * 256 + tid); return; }
    b -= PRE_W12;
    if (b < PRE_W12) { cvt_w_seg(Ws2, Wn2, 256, g_w[1], b * 256 + tid); return; }
    b -= PRE_W12;
    cvt_w_seg(Ws3, Wn3, 64, g_w3, b * 256 + tid);
}

// single-pass offsets
__global__ void k_off() {
    __shared__ int s[256];
    __shared__ int base;
    int i = blockIdx.x * 256 + threadIdx.x;
    int deg = (i < NN) ? g_degi[i] : 0;
    s[threadIdx.x] = deg;
    __syncthreads();
    for (int st = 1; st < 256; st <<= 1) {
        int add = (threadIdx.x >= st) ? s[threadIdx.x - st] : 0;
        __syncthreads();
        s[threadIdx.x] += add;
        __syncthreads();
    }
    if (threadIdx.x == 255) base = atomicAdd(&g_ctr, s[255]);
    __syncthreads();
    if (i < NN) {
        int beg = base + s[threadIdx.x] - deg;
        g_off[i] = beg;
        g_end[i] = beg + deg;
        g_cursor[i] = beg;
        g_inv[i] = 1.0f / fmaxf((float)deg, 1.0f);
        g_degi[i] = 0;
    }
}
// k_fill: CSR fill | cvt_x backfill
__global__ void k_fill(const int* __restrict__ src, const int* __restrict__ dst,
                       const float* __restrict__ x, int M, int E) {
    int b = blockIdx.x;
    int tid = threadIdx.x;
    if (b < FIL_E) {
        int e = b * 256 + tid;
        if (e < E) {
            int pos = atomicAdd(&g_cursor[__ldg(&dst[e])], 1);
            g_srcl[pos] = __ldg(&src[e]);
        }
        return;
    }
    b -= FIL_E;
    size_t i8 = (size_t)b * 256 + tid;
    int row = (int)(i8 >> 5);
    float4 v0 = make_float4(0.f, 0.f, 0.f, 0.f);
    float4 v1 = v0;
    if (row < M) {
        const float4* xp = reinterpret_cast<const float4*>(x) + i8 * 2;
        v0 = __ldg(xp);
        v1 = __ldg(xp + 1);
    }
    uint4 o;
    __half2 p0 = __float22half2_rn(make_float2(v0.x, v0.y));
    __half2 p1 = __float22half2_rn(make_float2(v0.z, v0.w));
    __half2 p2 = __float22half2_rn(make_float2(v1.x, v1.y));
    __half2 p3 = __float22half2_rn(make_float2(v1.z, v1.w));
    o.x = *reinterpret_cast<uint32_t*>(&p0);
    o.y = *reinterpret_cast<uint32_t*>(&p1);
    o.z = *reinterpret_cast<uint32_t*>(&p2);
    o.w = *reinterpret_cast<uint32_t*>(&p3);
    *reinterpret_cast<uint4*>(g_h + i8 * 8) = o;
}

// ---------------- fused gather + combine (unchanged from R12) ----------------
__device__ __forceinline__ void acc8(float* acc, uint4 raw) {
    const __half2* hp = reinterpret_cast<const __half2*>(&raw);
#pragma unroll
    for (int q = 0; q < 4; q++) {
        float2 f = __half22float2(hp[q]);
        acc[q * 2 + 0] += f.x;
        acc[q * 2 + 1] += f.y;
    }
}
__global__ void k_gather(const float* __restrict__ bias, int M) {
    int wid  = threadIdx.x >> 5;
    int lane = threadIdx.x & 31;
    int node = blockIdx.x * (blockDim.x >> 5) + wid;
    if (node >= M) return;
    int beg = g_off[node], end = g_end[node];
    const __half* z = g_yz + 256 + lane * 8;
    float acc[8] = {0.f, 0.f, 0.f, 0.f, 0.f, 0.f, 0.f, 0.f};
    int j = beg;
    for (; j + 4 <= end; j += 4) {
        int s0 = __ldg(&g_srcl[j]),     s1 = __ldg(&g_srcl[j + 1]);
        int s2 = __ldg(&g_srcl[j + 2]), s3 = __ldg(&g_srcl[j + 3]);
        uint4 r0 = __ldg(reinterpret_cast<const uint4*>(z + (size_t)s0 * 512));
        uint4 r1 = __ldg(reinterpret_cast<const uint4*>(z + (size_t)s1 * 512));
        uint4 r2 = __ldg(reinterpret_cast<const uint4*>(z + (size_t)s2 * 512));
        uint4 r3 = __ldg(reinterpret_cast<const uint4*>(z + (size_t)s3 * 512));
        acc8(acc, r0); acc8(acc, r1); acc8(acc, r2); acc8(acc, r3);
    }
    for (; j < end; j++) {
        int s0 = __ldg(&g_srcl[j]);
        uint4 r0 = __ldg(reinterpret_cast<const uint4*>(z + (size_t)s0 * 512));
        acc8(acc, r0);
    }
    float inv = g_inv[node];
    uint4 rs = __ldg(reinterpret_cast<const uint4*>(g_yz + (size_t)node * 512 + lane * 8));
    const __half2* sp = reinterpret_cast<const __half2*>(&rs);
    float4 bva = __ldg(reinterpret_cast<const float4*>(bias + lane * 8));
    float4 bvb = __ldg(reinterpret_cast<const float4*>(bias + lane * 8 + 4));
    float bv[8] = {bva.x, bva.y, bva.z, bva.w, bvb.x, bvb.y, bvb.z, bvb.w};
    float v[8];
#pragma unroll
    for (int q = 0; q < 4; q++) {
        float2 ys = __half22float2(sp[q]);
        v[q * 2 + 0] = fmaxf(ys.x + inv * acc[q * 2 + 0] + bv[q * 2 + 0], 0.f);
        v[q * 2 + 1] = fmaxf(ys.y + inv * acc[q * 2 + 1] + bv[q * 2 + 1], 0.f);
    }
    uint4 o;
    __half2 p0 = __float22half2_rn(make_float2(v[0], v[1]));
    __half2 p1 = __float22half2_rn(make_float2(v[2], v[3]));
    __half2 p2 = __float22half2_rn(make_float2(v[4], v[5]));
    __half2 p3 = __float22half2_rn(make_float2(v[6], v[7]));
    o.x = *reinterpret_cast<uint32_t*>(&p0);
    o.y = *reinterpret_cast<uint32_t*>(&p1);
    o.z = *reinterpret_cast<uint32_t*>(&p2);
    o.w = *reinterpret_cast<uint32_t*>(&p3);
    *reinterpret_cast<uint4*>(g_h + (size_t)node * 256 + lane * 8) = o;
}
__global__ void k_gather3(const float* __restrict__ bias, float* __restrict__ out, int M) {
    int wid  = threadIdx.x >> 5;
    int lane = threadIdx.x & 31;
    int node = (blockIdx.x * (blockDim.x >> 5) + wid) * 4 + (lane >> 3);
    int sub  = lane & 7;
    if (node >= M) return;
    int beg = g_off[node], end = g_end[node];
    const __half* z = g_yz + 64 + sub * 8;
    float acc[8] = {0.f, 0.f, 0.f, 0.f, 0.f, 0.f, 0.f, 0.f};
    int j = beg;
    for (; j + 4 <= end; j += 4) {
        int s0 = __ldg(&g_srcl[j]),     s1 = __ldg(&g_srcl[j + 1]);
        int s2 = __ldg(&g_srcl[j + 2]), s3 = __ldg(&g_srcl[j + 3]);
        uint4 r0 = __ldg(reinterpret_cast<const uint4*>(z + (size_t)s0 * 128));
        uint4 r1 = __ldg(reinterpret_cast<const uint4*>(z + (size_t)s1 * 128));
        uint4 r2 = __ldg(reinterpret_cast<const uint4*>(z + (size_t)s2 * 128));
        uint4 r3 = __ldg(reinterpret_cast<const uint4*>(z + (size_t)s3 * 128));
        acc8(acc, r0); acc8(acc, r1); acc8(acc, r2); acc8(acc, r3);
    }
    for (; j < end; j++) {
        int s0 = __ldg(&g_srcl[j]);
        uint4 r0 = __ldg(reinterpret_cast<const uint4*>(z + (size_t)s0 * 128));
        acc8(acc, r0);
    }
    float inv = g_inv[node];
    uint4 rs = __ldg(reinterpret_cast<const uint4*>(g_yz + (size_t)node * 128 + sub * 8));
    const __half2* sp = reinterpret_cast<const __half2*>(&rs);
    float4 bva = __ldg(reinterpret_cast<const float4*>(bias + sub * 8));
    float4 bvb = __ldg(reinterpret_cast<const float4*>(bias + sub * 8 + 4));
    float bv[8] = {bva.x, bva.y, bva.z, bva.w, bvb.x, bvb.y, bvb.z, bvb.w};
    float v[8];
#pragma unroll
    for (int q = 0; q < 4; q++) {
        float2 ys = __half22float2(sp[q]);
        v[q * 2 + 0] = ys.x + inv * acc[q * 2 + 0] + bv[q * 2 + 0];
        v[q * 2 + 1] = ys.y + inv * acc[q * 2 + 1] + bv[q * 2 + 1];
    }
    float* op = out + (size_t)node * 64 + sub * 8;
    *reinterpret_cast<float4*>(op)     = make_float4(v[0], v[1], v[2], v[3]);
    *reinterpret_cast<float4*>(op + 4) = make_float4(v[4], v[5], v[6], v[7]);
}

// ---------------- fp16 HMMA GEMM with TMA tile loads ----------------
// CTA tile 128x128, BK=64, 3-stage TMA ring (SW128 swizzle), 8 warps (2m x 4n),
// warp tile 64x32, 2 CTAs/SM. Tiles: A/B each 128 rows x 128B.
#define TSTG 32768             // bytes per stage (A 16KB + B 16KB)
#define SMEM_DYN (3 * TSTG + 128)

__global__ __launch_bounds__(256, 2) void k_mma(
    const __grid_constant__ CUtensorMap mapA,
    const __grid_constant__ CUtensorMap mapB,
    __half* __restrict__ Y, int NOUT)
{
    extern __shared__ __align__(1024) char dyn[];
    const uint32_t sb = smem_u32(dyn);
    const uint32_t barB = sb + 3 * TSTG;   // 3 mbarriers (8B each)

    const int t    = threadIdx.x;
    const int wid  = t >> 5;
    const int lane = t & 31;
    const int wm0  = (wid >> 2) << 6;
    const int wn0  = (wid & 3) << 5;
    const int row0 = blockIdx.y * 128;
    const int col0 = blockIdx.x * 128;

    if (t == 0) {
#pragma unroll
        for (int s = 0; s < 3; s++)
            asm volatile("mbarrier.init.shared.b64 [%0], 1;" :: "r"(barB + s * 8) : "memory");
    }
    __syncthreads();

    auto issue = [&](int kc, int s) {
        uint32_t bar = barB + s * 8;
        asm volatile("mbarrier.arrive.expect_tx.shared.b64 _, [%0], %1;"
                     :: "r"(bar), "r"(32768u) : "memory");
        asm volatile("cp.async.bulk.tensor.2d.shared::cta.global.tile.mbarrier::complete_tx::bytes "
                     "[%0], [%1, {%2, %3}], [%4];"
                     :: "r"(sb + s * TSTG), "l"(&mapA), "r"(kc * 64), "r"(row0), "r"(bar)
                     : "memory");
        asm volatile("cp.async.bulk.tensor.2d.shared::cta.global.tile.mbarrier::complete_tx::bytes "
                     "[%0], [%1, {%2, %3}], [%4];"
                     :: "r"(sb + s * TSTG + 16384), "l"(&mapB), "r"(kc * 64), "r"(col0), "r"(bar)
                     : "memory");
    };
    if (t == 0) {
        issue(0, 0); issue(1, 1); issue(2, 2);
    }

    float acc[4][4][4];
#pragma unroll
    for (int mi = 0; mi < 4; mi++)
#pragma unroll
        for (int ni = 0; ni < 4; ni++)
#pragma unroll
            for (int r = 0; r < 4; r++) acc[mi][ni][r] = 0.0f;

#pragma unroll
    for (int kc = 0; kc < 4; kc++) {
        const int s = kc % 3;
        const uint32_t ph = (uint32_t)(kc / 3);
        {
            uint32_t bar = barB + s * 8;
            asm volatile("{\n\t.reg .pred P;\n\tWL%=:\n\t"
                         "mbarrier.try_wait.parity.acquire.cta.shared::cta.b64 P, [%0], %1, 0x989680;\n\t"
                         "@!P bra WL%=;\n\t}" :: "r"(bar), "r"(ph) : "memory");
        }

        const uint32_t tA = sb + s * TSTG;
        const uint32_t tB = tA + 16384;

#pragma unroll
        for (int ks = 0; ks < 4; ks++) {
            const int arow = wm0 + (lane & 15);
            const int abyte = ks * 32 + ((lane >> 4) << 4);   // (k0 + 0/8 halves)*2
            const int brow = wn0 + (lane & 7) + ((lane >> 4) << 3);
            const int bbyte = ks * 32 + (((lane >> 3) & 1) << 4);

            uint32_t a[4][4], b[8];
#pragma unroll
            for (int mi = 0; mi < 4; mi++) {
                uint32_t off = (arow + mi * 16) * 128 + abyte;
                uint32_t ad = tA + SWZ(off);
                asm volatile("ldmatrix.sync.aligned.m8n8.x4.shared.b16 {%0,%1,%2,%3}, [%4];"
                             : "=r"(a[mi][0]), "=r"(a[mi][1]), "=r"(a[mi][2]), "=r"(a[mi][3])
                             : "r"(ad));
            }
#pragma unroll
            for (int nb = 0; nb < 2; nb++) {
                uint32_t off = (brow + nb * 16) * 128 + bbyte;
                uint32_t ad = tB + SWZ(off);
                asm volatile("ldmatrix.sync.aligned.m8n8.x4.shared.b16 {%0,%1,%2,%3}, [%4];"
                             : "=r"(b[nb * 4 + 0]), "=r"(b[nb * 4 + 1]),
                               "=r"(b[nb * 4 + 2]), "=r"(b[nb * 4 + 3])
                             : "r"(ad));
            }
#pragma unroll
            for (int mi = 0; mi < 4; mi++)
#pragma unroll
                for (int ni = 0; ni < 4; ni++)
                    asm volatile(
                        "mma.sync.aligned.m16n8k16.row.col.f32.f16.f16.f32 "
                        "{%0,%1,%2,%3}, {%4,%5,%6,%7}, {%8,%9}, {%0,%1,%2,%3};"
                        : "+f"(acc[mi][ni][0]), "+f"(acc[mi][ni][1]),
                          "+f"(acc[mi][ni][2]), "+f"(acc[mi][ni][3])
                        : "r"(a[mi][0]), "r"(a[mi][1]), "r"(a[mi][2]), "r"(a[mi][3]),
                          "r"(b[ni * 2]), "r"(b[ni * 2 + 1]));
        }
        if (kc == 0) {
            __syncthreads();               // all warps done reading stage 0
            if (t == 0) issue(3, 0);       // refill stage 0 with chunk 3 (phase 1)
        }
    }

    const int crow = lane >> 2;
    const int ccol = (lane & 3) << 1;
#pragma unroll
    for (int mi = 0; mi < 4; mi++)
#pragma unroll
        for (int ni = 0; ni < 4; ni++) {
            int col = col0 + wn0 + ni * 8 + ccol;
#pragma unroll
            for (int h = 0; h < 2; h++) {
                int row = row0 + wm0 + mi * 16 + crow + h * 8;
                __half2 p = __float22half2_rn(
                    make_float2(acc[mi][ni][h * 2 + 0], acc[mi][ni][h * 2 + 1]));
                *reinterpret_cast<uint32_t*>(Y + (size_t)row * NOUT + col) =
                    *reinterpret_cast<uint32_t*>(&p);
            }
        }
}

// ---------------- launch ----------------
typedef CUresult (*PFN_tme)(CUtensorMap*, CUtensorMapDataType, cuuint32_t, void*,
                            const cuuint64_t*, const cuuint64_t*, const cuuint32_t*,
                            const cuuint32_t*, CUtensorMapInterleave, CUtensorMapSwizzle,
                            CUtensorMapL2promotion, CUtensorMapFloatOOBfill);

extern "C" void kernel_launch(void* const* d_in, const int* in_sizes, int n_in,
                              void* d_out, int out_size) {
    const float* x   = (const float*)d_in[0];
    const int*   src = (const int*)d_in[1];
    const int*   dst = (const int*)d_in[2];
    const float* Ws1 = (const float*)d_in[3];
    const float* Wn1 = (const float*)d_in[4];
    const float* b1  = (const float*)d_in[5];
    const float* Ws2 = (const float*)d_in[6];
    const float* Wn2 = (const float*)d_in[7];
    const float* b2  = (const float*)d_in[8];
    const float* Ws3 = (const float*)d_in[9];
    const float* Wn3 = (const float*)d_in[10];
    const float* b3  = (const float*)d_in[11];
    float* out = (float*)d_out;

    const int N = in_sizes[0] / FEAT;   // 100000
    const int E = in_sizes[1];          // 800000

    __half *yz, *h, *w0, *w1, *w3;
    cudaGetSymbolAddress((void**)&yz, g_yz);
    cudaGetSymbolAddress((void**)&h,  g_h);
    cudaGetSymbolAddress((void**)&w0, g_w);
    cudaGetSymbolAddress((void**)&w3, g_w3);
    w1 = w0 + (size_t)512 * 256;

    // --- TMA tensor maps (encoded host-side; captured by value) ---
    static PFN_tme enc = nullptr;
    if (!enc) {
        void* fn = nullptr;
        cudaDriverEntryPointQueryResult qr;
        cudaGetDriverEntryPoint("cuTensorMapEncodeTiled", &fn, cudaEnableDefault, &qr);
        enc = (PFN_tme)fn;
    }
    static CUtensorMap mH, mW0, mW1, mW3;
    auto mk = [&](CUtensorMap* m, void* ptr, uint64_t rows) {
        cuuint64_t dims[2]    = {256, rows};
        cuuint64_t strides[1] = {512};              // bytes per row
        cuuint32_t box[2]     = {64, 128};
        cuuint32_t es[2]      = {1, 1};
        enc(m, CU_TENSOR_MAP_DATA_TYPE_FLOAT16, 2, ptr, dims, strides, box, es,
            CU_TENSOR_MAP_INTERLEAVE_NONE, CU_TENSOR_MAP_SWIZZLE_128B,
            CU_TENSOR_MAP_L2_PROMOTION_L2_128B, CU_TENSOR_MAP_FLOAT_OOB_FILL_NONE);
    };
    mk(&mH,  h,  MPAD);
    mk(&mW0, w0, 512);
    mk(&mW1, w1, 512);
    mk(&mW3, w3, 128);

    cudaFuncSetAttribute(k_mma, cudaFuncAttributeMaxDynamicSharedMemorySize, SMEM_DYN);

    const int ZT = 256;

    k_pre<<<PRE_DEGI + 2 * PRE_W12 + 128, ZT>>>(dst, Ws1, Wn1, Ws2, Wn2, Ws3, Wn3, E);
    k_off<<<NB, 256>>>();
    k_fill<<<FIL_E + FIL_CVTX, ZT>>>(src, dst, x, N, E);

    dim3 g12(4, NT);
    dim3 g3(1, NT);
    const int gatherB = (N + 7) / 8;
    const int gather3B = (N + 31) / 32;

    // layer 1
    k_mma<<<g12, 256, SMEM_DYN>>>(mH, mW0, yz, 512);
    k_gather<<<gatherB, 256>>>(b1, N);

    // layer 2
    k_mma<<<g12, 256, SMEM_DYN>>>(mH, mW1, yz, 512);
    k_gather<<<gatherB, 256>>>(b2, N);

    // layer 3
    k_mma<<<g3, 256, SMEM_DYN>>>(mH, mW3, yz, 128);
    k_gather3<<<gather3B, 256>>>(b3, out, N);
}

// round 14
// speedup vs baseline: 1.2308x; 1.0051x over previous
#include <cuda.h>
#include <cuda_runtime.h>
#include <cuda_fp16.h>
#include <cstdint>

#define NN   100000
#define MPAD 100096            // 782 * 128
#define FEAT 256
#define NT   782
#define EMAX 800000
#define NB   391               // ceil(NN/256)

// k_pre block ranges: degi | cvt_w x3
#define PRE_DEGI 3125
#define PRE_W12  512
// k_fill block ranges: fill | cvt_x
#define FIL_E    3125
#define FIL_CVTX 12512         // MPAD*256/8/256

// ---------------- device scratch ----------------
__device__ int   g_degi[NN];
__device__ int   g_ctr;
__device__ float g_inv[NN];
__device__ int   g_off[NN];
__device__ int   g_end[NN];
__device__ int   g_cursor[NN];
__device__ int   g_srcl[EMAX];
__device__ __align__(16) __half g_yz[(size_t)MPAD * 512];
__device__ __align__(16) __half g_h[(size_t)MPAD * FEAT];
__device__ __align__(16) __half g_w[2][512 * 256];
__device__ __align__(16) __half g_w3[128 * 256];

// ---------------- helpers ----------------
__device__ __forceinline__ uint32_t smem_u32(const void* p) {
    uint32_t a;
    asm("{ .reg .u64 t; cvta.to.shared.u64 t, %1; cvt.u32.u64 %0, t; }" : "=r"(a) : "l"(p));
    return a;
}
#define SWZ(off) ((off) ^ (((off) >> 3) & 0x70))

__device__ __forceinline__ void cvt_w_seg(const float* __restrict__ Ws,
                                          const float* __restrict__ Wn,
                                          int Nw, __half* __restrict__ w, int idx) {
    int n = idx >> 8, k = idx & 255;
    float v = (n < Nw) ? __ldg(&Ws[(size_t)k * Nw + n]) : __ldg(&Wn[(size_t)k * Nw + (n - Nw)]);
    w[idx] = __float2half_rn(v);
}

// ---------------- k_pre: degi | cvt_w x3 ----------------
__global__ void k_pre(const int* __restrict__ dst,
                      const float* __restrict__ Ws1, const float* __restrict__ Wn1,
                      const float* __restrict__ Ws2, const float* __restrict__ Wn2,
                      const float* __restrict__ Ws3, const float* __restrict__ Wn3,
                      int E) {
    int b = blockIdx.x;
    int tid = threadIdx.x;
    if (b == 0 && tid == 0) g_ctr = 0;
    if (b < PRE_DEGI) {
        int e = b * 256 + tid;
        if (e < E) atomicAdd(&g_degi[__ldg(&dst[e])], 1);
        return;
    }
    b -= PRE_DEGI;
    if (b < PRE_W12) { cvt_w_seg(Ws1, Wn1, 256, g_w[0], b * 256 + tid); return; }
    b -= PRE_W12;
    if (b < PRE_W12) { cvt_w_seg(Ws2, Wn2, 256, g_w[1], b * 256 + tid); return; }
    b -= PRE_W12;
    cvt_w_seg(Ws3, Wn3, 64, g_w3, b * 256 + tid);
}

// single-pass offsets
__global__ void k_off() {
    __shared__ int s[256];
    __shared__ int base;
    int i = blockIdx.x * 256 + threadIdx.x;
    int deg = (i < NN) ? g_degi[i] : 0;
    s[threadIdx.x] = deg;
    __syncthreads();
    for (int st = 1; st < 256; st <<= 1) {
        int add = (threadIdx.x >= st) ? s[threadIdx.x - st] : 0;
        __syncthreads();
        s[threadIdx.x] += add;
        __syncthreads();
    }
    if (threadIdx.x == 255) base = atomicAdd(&g_ctr, s[255]);
    __syncthreads();
    if (i < NN) {
        int beg = base + s[threadIdx.x] - deg;
        g_off[i] = beg;
        g_end[i] = beg + deg;
        g_cursor[i] = beg;
        g_inv[i] = 1.0f / fmaxf((float)deg, 1.0f);
        g_degi[i] = 0;
    }
}
// k_fill: CSR fill | cvt_x backfill
__global__ void k_fill(const int* __restrict__ src, const int* __restrict__ dst,
                       const float* __restrict__ x, int M, int E) {
    int b = blockIdx.x;
    int tid = threadIdx.x;
    if (b < FIL_E) {
        int e = b * 256 + tid;
        if (e < E) {
            int pos = atomicAdd(&g_cursor[__ldg(&dst[e])], 1);
            g_srcl[pos] = __ldg(&src[e]);
        }
        return;
    }
    b -= FIL_E;
    size_t i8 = (size_t)b * 256 + tid;
    int row = (int)(i8 >> 5);
    float4 v0 = make_float4(0.f, 0.f, 0.f, 0.f);
    float4 v1 = v0;
    if (row < M) {
        const float4* xp = reinterpret_cast<const float4*>(x) + i8 * 2;
        v0 = __ldg(xp);
        v1 = __ldg(xp + 1);
    }
    uint4 o;
    __half2 p0 = __float22half2_rn(make_float2(v0.x, v0.y));
    __half2 p1 = __float22half2_rn(make_float2(v0.z, v0.w));
    __half2 p2 = __float22half2_rn(make_float2(v1.x, v1.y));
    __half2 p3 = __float22half2_rn(make_float2(v1.z, v1.w));
    o.x = *reinterpret_cast<uint32_t*>(&p0);
    o.y = *reinterpret_cast<uint32_t*>(&p1);
    o.z = *reinterpret_cast<uint32_t*>(&p2);
    o.w = *reinterpret_cast<uint32_t*>(&p3);
    *reinterpret_cast<uint4*>(g_h + i8 * 8) = o;
}

// ---------------- fused gather + combine (unchanged) ----------------
__device__ __forceinline__ void acc8(float* acc, uint4 raw) {
    const __half2* hp = reinterpret_cast<const __half2*>(&raw);
#pragma unroll
    for (int q = 0; q < 4; q++) {
        float2 f = __half22float2(hp[q]);
        acc[q * 2 + 0] += f.x;
        acc[q * 2 + 1] += f.y;
    }
}
__global__ void k_gather(const float* __restrict__ bias, int M) {
    int wid  = threadIdx.x >> 5;
    int lane = threadIdx.x & 31;
    int node = blockIdx.x * (blockDim.x >> 5) + wid;
    if (node >= M) return;
    int beg = g_off[node], end = g_end[node];
    const __half* z = g_yz + 256 + lane * 8;
    float acc[8] = {0.f, 0.f, 0.f, 0.f, 0.f, 0.f, 0.f, 0.f};
    int j = beg;
    for (; j + 4 <= end; j += 4) {
        int s0 = __ldg(&g_srcl[j]),     s1 = __ldg(&g_srcl[j + 1]);
        int s2 = __ldg(&g_srcl[j + 2]), s3 = __ldg(&g_srcl[j + 3]);
        uint4 r0 = __ldg(reinterpret_cast<const uint4*>(z + (size_t)s0 * 512));
        uint4 r1 = __ldg(reinterpret_cast<const uint4*>(z + (size_t)s1 * 512));
        uint4 r2 = __ldg(reinterpret_cast<const uint4*>(z + (size_t)s2 * 512));
        uint4 r3 = __ldg(reinterpret_cast<const uint4*>(z + (size_t)s3 * 512));
        acc8(acc, r0); acc8(acc, r1); acc8(acc, r2); acc8(acc, r3);
    }
    for (; j < end; j++) {
        int s0 = __ldg(&g_srcl[j]);
        uint4 r0 = __ldg(reinterpret_cast<const uint4*>(z + (size_t)s0 * 512));
        acc8(acc, r0);
    }
    float inv = g_inv[node];
    uint4 rs = __ldg(reinterpret_cast<const uint4*>(g_yz + (size_t)node * 512 + lane * 8));
    const __half2* sp = reinterpret_cast<const __half2*>(&rs);
    float4 bva = __ldg(reinterpret_cast<const float4*>(bias + lane * 8));
    float4 bvb = __ldg(reinterpret_cast<const float4*>(bias + lane * 8 + 4));
    float bv[8] = {bva.x, bva.y, bva.z, bva.w, bvb.x, bvb.y, bvb.z, bvb.w};
    float v[8];
#pragma unroll
    for (int q = 0; q < 4; q++) {
        float2 ys = __half22float2(sp[q]);
        v[q * 2 + 0] = fmaxf(ys.x + inv * acc[q * 2 + 0] + bv[q * 2 + 0], 0.f);
        v[q * 2 + 1] = fmaxf(ys.y + inv * acc[q * 2 + 1] + bv[q * 2 + 1], 0.f);
    }
    uint4 o;
    __half2 p0 = __float22half2_rn(make_float2(v[0], v[1]));
    __half2 p1 = __float22half2_rn(make_float2(v[2], v[3]));
    __half2 p2 = __float22half2_rn(make_float2(v[4], v[5]));
    __half2 p3 = __float22half2_rn(make_float2(v[6], v[7]));
    o.x = *reinterpret_cast<uint32_t*>(&p0);
    o.y = *reinterpret_cast<uint32_t*>(&p1);
    o.z = *reinterpret_cast<uint32_t*>(&p2);
    o.w = *reinterpret_cast<uint32_t*>(&p3);
    *reinterpret_cast<uint4*>(g_h + (size_t)node * 256 + lane * 8) = o;
}
__global__ void k_gather3(const float* __restrict__ bias, float* __restrict__ out, int M) {
    int wid  = threadIdx.x >> 5;
    int lane = threadIdx.x & 31;
    int node = (blockIdx.x * (blockDim.x >> 5) + wid) * 4 + (lane >> 3);
    int sub  = lane & 7;
    if (node >= M) return;
    int beg = g_off[node], end = g_end[node];
    const __half* z = g_yz + 64 + sub * 8;
    float acc[8] = {0.f, 0.f, 0.f, 0.f, 0.f, 0.f, 0.f, 0.f};
    int j = beg;
    for (; j + 4 <= end; j += 4) {
        int s0 = __ldg(&g_srcl[j]),     s1 = __ldg(&g_srcl[j + 1]);
        int s2 = __ldg(&g_srcl[j + 2]), s3 = __ldg(&g_srcl[j + 3]);
        uint4 r0 = __ldg(reinterpret_cast<const uint4*>(z + (size_t)s0 * 128));
        uint4 r1 = __ldg(reinterpret_cast<const uint4*>(z + (size_t)s1 * 128));
        uint4 r2 = __ldg(reinterpret_cast<const uint4*>(z + (size_t)s2 * 128));
        uint4 r3 = __ldg(reinterpret_cast<const uint4*>(z + (size_t)s3 * 128));
        acc8(acc, r0); acc8(acc, r1); acc8(acc, r2); acc8(acc, r3);
    }
    for (; j < end; j++) {
        int s0 = __ldg(&g_srcl[j]);
        uint4 r0 = __ldg(reinterpret_cast<const uint4*>(z + (size_t)s0 * 128));
        acc8(acc, r0);
    }
    float inv = g_inv[node];
    uint4 rs = __ldg(reinterpret_cast<const uint4*>(g_yz + (size_t)node * 128 + sub * 8));
    const __half2* sp = reinterpret_cast<const __half2*>(&rs);
    float4 bva = __ldg(reinterpret_cast<const float4*>(bias + sub * 8));
    float4 bvb = __ldg(reinterpret_cast<const float4*>(bias + sub * 8 + 4));
    float bv[8] = {bva.x, bva.y, bva.z, bva.w, bvb.x, bvb.y, bvb.z, bvb.w};
    float v[8];
#pragma unroll
    for (int q = 0; q < 4; q++) {
        float2 ys = __half22float2(sp[q]);
        v[q * 2 + 0] = ys.x + inv * acc[q * 2 + 0] + bv[q * 2 + 0];
        v[q * 2 + 1] = ys.y + inv * acc[q * 2 + 1] + bv[q * 2 + 1];
    }
    float* op = out + (size_t)node * 64 + sub * 8;
    *reinterpret_cast<float4*>(op)     = make_float4(v[0], v[1], v[2], v[3]);
    *reinterpret_cast<float4*>(op + 4) = make_float4(v[4], v[5], v[6], v[7]);
}

// ---------------- fp16 HMMA GEMM, TMA loads, 128 threads, warp tile 64x64 ----------------
// CTA tile 128x128, BK=64, 3-stage TMA ring (SW128), 4 warps (2m x 2n), 2 CTAs/SM.
#define TSTG 32768
#define SMEM_DYN (3 * TSTG + 128)

__global__ __launch_bounds__(128, 2) void k_mma(
    const __grid_constant__ CUtensorMap mapA,
    const __grid_constant__ CUtensorMap mapB,
    __half* __restrict__ Y, int NOUT)
{
    extern __shared__ __align__(1024) char dyn[];
    const uint32_t sb = smem_u32(dyn);
    const uint32_t barB = sb + 3 * TSTG;

    const int t    = threadIdx.x;
    const int wid  = t >> 5;
    const int lane = t & 31;
    const int wm0  = (wid >> 1) << 6;     // 0 or 64
    const int wn0  = (wid & 1) << 6;      // 0 or 64
    const int row0 = blockIdx.y * 128;
    const int col0 = blockIdx.x * 128;

    if (t == 0) {
#pragma unroll
        for (int s = 0; s < 3; s++)
            asm volatile("mbarrier.init.shared.b64 [%0], 1;" :: "r"(barB + s * 8) : "memory");
    }
    __syncthreads();

    auto issue = [&](int kc, int s) {
        uint32_t bar = barB + s * 8;
        asm volatile("mbarrier.arrive.expect_tx.shared.b64 _, [%0], %1;"
                     :: "r"(bar), "r"(32768u) : "memory");
        asm volatile("cp.async.bulk.tensor.2d.shared::cta.global.tile.mbarrier::complete_tx::bytes "
                     "[%0], [%1, {%2, %3}], [%4];"
                     :: "r"(sb + s * TSTG), "l"(&mapA), "r"(kc * 64), "r"(row0), "r"(bar)
                     : "memory");
        asm volatile("cp.async.bulk.tensor.2d.shared::cta.global.tile.mbarrier::complete_tx::bytes "
                     "[%0], [%1, {%2, %3}], [%4];"
                     :: "r"(sb + s * TSTG + 16384), "l"(&mapB), "r"(kc * 64), "r"(col0), "r"(bar)
                     : "memory");
    };
    if (t == 0) {
        issue(0, 0); issue(1, 1); issue(2, 2);
    }

    float acc[4][8][4];
#pragma unroll
    for (int mi = 0; mi < 4; mi++)
#pragma unroll
        for (int ni = 0; ni < 8; ni++)
#pragma unroll
            for (int r = 0; r < 4; r++) acc[mi][ni][r] = 0.0f;

#pragma unroll
    for (int kc = 0; kc < 4; kc++) {
        const int s = kc % 3;
        const uint32_t ph = (uint32_t)(kc / 3);
        {
            uint32_t bar = barB + s * 8;
            asm volatile("{\n\t.reg .pred P;\n\tWL%=:\n\t"
                         "mbarrier.try_wait.parity.acquire.cta.shared::cta.b64 P, [%0], %1, 0x989680;\n\t"
                         "@!P bra WL%=;\n\t}" :: "r"(bar), "r"(ph) : "memory");
        }

        const uint32_t tA = sb + s * TSTG;
        const uint32_t tB = tA + 16384;

#pragma unroll
        for (int ks = 0; ks < 4; ks++) {
            const int arow = wm0 + (lane & 15);
            const int abyte = ks * 32 + ((lane >> 4) << 4);
            const int brow = wn0 + (lane & 7) + ((lane >> 4) << 3);
            const int bbyte = ks * 32 + (((lane >> 3) & 1) << 4);

            uint32_t a[4][4], b[16];
#pragma unroll
            for (int mi = 0; mi < 4; mi++) {
                uint32_t off = (arow + mi * 16) * 128 + abyte;
                uint32_t ad = tA + SWZ(off);
                asm volatile("ldmatrix.sync.aligned.m8n8.x4.shared.b16 {%0,%1,%2,%3}, [%4];"
                             : "=r"(a[mi][0]), "=r"(a[mi][1]), "=r"(a[mi][2]), "=r"(a[mi][3])
                             : "r"(ad));
            }
#pragma unroll
            for (int nb = 0; nb < 4; nb++) {
                uint32_t off = (brow + nb * 16) * 128 + bbyte;
                uint32_t ad = tB + SWZ(off);
                asm volatile("ldmatrix.sync.aligned.m8n8.x4.shared.b16 {%0,%1,%2,%3}, [%4];"
                             : "=r"(b[nb * 4 + 0]), "=r"(b[nb * 4 + 1]),
                               "=r"(b[nb * 4 + 2]), "=r"(b[nb * 4 + 3])
                             : "r"(ad));
            }
#pragma unroll
            for (int mi = 0; mi < 4; mi++)
#pragma unroll
                for (int ni = 0; ni < 8; ni++)
                    asm volatile(
                        "mma.sync.aligned.m16n8k16.row.col.f32.f16.f16.f32 "
                        "{%0,%1,%2,%3}, {%4,%5,%6,%7}, {%8,%9}, {%0,%1,%2,%3};"
                        : "+f"(acc[mi][ni][0]), "+f"(acc[mi][ni][1]),
                          "+f"(acc[mi][ni][2]), "+f"(acc[mi][ni][3])
                        : "r"(a[mi][0]), "r"(a[mi][1]), "r"(a[mi][2]), "r"(a[mi][3]),
                          "r"(b[ni * 2]), "r"(b[ni * 2 + 1]));
        }
        if (kc == 0) {
            __syncthreads();
            if (t == 0) issue(3, 0);
        }
    }

    const int crow = lane >> 2;
    const int ccol = (lane & 3) << 1;
#pragma unroll
    for (int mi = 0; mi < 4; mi++)
#pragma unroll
        for (int ni = 0; ni < 8; ni++) {
            int col = col0 + wn0 + ni * 8 + ccol;
#pragma unroll
            for (int h = 0; h < 2; h++) {
                int row = row0 + wm0 + mi * 16 + crow + h * 8;
                __half2 p = __float22half2_rn(
                    make_float2(acc[mi][ni][h * 2 + 0], acc[mi][ni][h * 2 + 1]));
                *reinterpret_cast<uint32_t*>(Y + (size_t)row * NOUT + col) =
                    *reinterpret_cast<uint32_t*>(&p);
            }
        }
}

// ---------------- launch ----------------
typedef CUresult (*PFN_tme)(CUtensorMap*, CUtensorMapDataType, cuuint32_t, void*,
                            const cuuint64_t*, const cuuint64_t*, const cuuint32_t*,
                            const cuuint32_t*, CUtensorMapInterleave, CUtensorMapSwizzle,
                            CUtensorMapL2promotion, CUtensorMapFloatOOBfill);

extern "C" void kernel_launch(void* const* d_in, const int* in_sizes, int n_in,
                              void* d_out, int out_size) {
    const float* x   = (const float*)d_in[0];
    const int*   src = (const int*)d_in[1];
    const int*   dst = (const int*)d_in[2];
    const float* Ws1 = (const float*)d_in[3];
    const float* Wn1 = (const float*)d_in[4];
    const float* b1  = (const float*)d_in[5];
    const float* Ws2 = (const float*)d_in[6];
    const float* Wn2 = (const float*)d_in[7];
    const float* b2  = (const float*)d_in[8];
    const float* Ws3 = (const float*)d_in[9];
    const float* Wn3 = (const float*)d_in[10];
    const float* b3  = (const float*)d_in[11];
    float* out = (float*)d_out;

    const int N = in_sizes[0] / FEAT;   // 100000
    const int E = in_sizes[1];          // 800000

    __half *yz, *h, *w0, *w1, *w3;
    cudaGetSymbolAddress((void**)&yz, g_yz);
    cudaGetSymbolAddress((void**)&h,  g_h);
    cudaGetSymbolAddress((void**)&w0, g_w);
    cudaGetSymbolAddress((void**)&w3, g_w3);
    w1 = w0 + (size_t)512 * 256;

    static PFN_tme enc = nullptr;
    if (!enc) {
        void* fn = nullptr;
        cudaDriverEntryPointQueryResult qr;
        cudaGetDriverEntryPoint("cuTensorMapEncodeTiled", &fn, cudaEnableDefault, &qr);
        enc = (PFN_tme)fn;
    }
    static CUtensorMap mH, mW0, mW1, mW3;
    auto mk = [&](CUtensorMap* m, void* ptr, uint64_t rows) {
        cuuint64_t dims[2]    = {256, rows};
        cuuint64_t strides[1] = {512};
        cuuint32_t box[2]     = {64, 128};
        cuuint32_t es[2]      = {1, 1};
        enc(m, CU_TENSOR_MAP_DATA_TYPE_FLOAT16, 2, ptr, dims, strides, box, es,
            CU_TENSOR_MAP_INTERLEAVE_NONE, CU_TENSOR_MAP_SWIZZLE_128B,
            CU_TENSOR_MAP_L2_PROMOTION_L2_128B, CU_TENSOR_MAP_FLOAT_OOB_FILL_NONE);
    };
    mk(&mH,  h,  MPAD);
    mk(&mW0, w0, 512);
    mk(&mW1, w1, 512);
    mk(&mW3, w3, 128);

    cudaFuncSetAttribute(k_mma, cudaFuncAttributeMaxDynamicSharedMemorySize, SMEM_DYN);

    const int ZT = 256;

    k_pre<<<PRE_DEGI + 2 * PRE_W12 + 128, ZT>>>(dst, Ws1, Wn1, Ws2, Wn2, Ws3, Wn3, E);
    k_off<<<NB, 256>>>();
    k_fill<<<FIL_E + FIL_CVTX, ZT>>>(src, dst, x, N, E);

    dim3 g12(4, NT);
    dim3 g3(1, NT);
    const int gatherB = (N + 7) / 8;
    const int gather3B = (N + 31) / 32;

    // layer 1
    k_mma<<<g12, 128, SMEM_DYN>>>(mH, mW0, yz, 512);
    k_gather<<<gatherB, 256>>>(b1, N);

    // layer 2
    k_mma<<<g12, 128, SMEM_DYN>>>(mH, mW1, yz, 512);
    k_gather<<<gatherB, 256>>>(b2, N);

    // layer 3
    k_mma<<<g3, 128, SMEM_DYN>>>(mH, mW3, yz, 128);
    k_gather3<<<gather3B, 256>>>(b3, out, N);
}